// round 5
// baseline (speedup 1.0000x reference)
#include <cuda_runtime.h>
#include <cuda_bf16.h>
#include <math_constants.h>

#define NB 16384      // batch rows
#define NP 4096       // passages per row
#define THREADS 256
#define CHUNKS 4      // 4 float4 per thread: 256 threads * 4 * 4 floats = 4096

// Per-row loss scratch (no dynamic allocation allowed).
__device__ float g_rowloss[NB];

__global__ __launch_bounds__(THREADS)
void mpnl_row_kernel(const float* __restrict__ logits,
                     const int* __restrict__ labels)   // int32: JAX demotes int64
{
    const int row = blockIdx.x;
    const int t   = threadIdx.x;

    const float4* lg4 = (const float4*)(logits + (size_t)row * NP);
    const int4*   lb4 = (const int4*)(labels + (size_t)row * NP);

    // Load 16 logits + 16 labels per thread; stash logits in registers,
    // labels as a 16-bit mask. Coalesced 16B accesses, same index stream
    // for both tensors.
    float v[16];
    unsigned mask = 0u;
    float m = -CUDART_INF_F;

    #pragma unroll
    for (int c = 0; c < CHUNKS; c++) {
        const int idx = c * THREADS + t;          // vec4 index within row
        float4 f = lg4[idx];
        int4   l = lb4[idx];

        v[c * 4 + 0] = f.x;
        v[c * 4 + 1] = f.y;
        v[c * 4 + 2] = f.z;
        v[c * 4 + 3] = f.w;
        if (l.x != 0) mask |= 1u << (c * 4 + 0);
        if (l.y != 0) mask |= 1u << (c * 4 + 1);
        if (l.z != 0) mask |= 1u << (c * 4 + 2);
        if (l.w != 0) mask |= 1u << (c * 4 + 3);

        m = fmaxf(m, fmaxf(fmaxf(f.x, f.y), fmaxf(f.z, f.w)));
    }

    // ---- Block-reduce the row max ----
    __shared__ float s_max[THREADS / 32];
    #pragma unroll
    for (int o = 16; o > 0; o >>= 1)
        m = fmaxf(m, __shfl_xor_sync(0xffffffffu, m, o));
    if ((t & 31) == 0) s_max[t >> 5] = m;
    __syncthreads();

    float rowmax = s_max[0];
    #pragma unroll
    for (int i = 1; i < THREADS / 32; i++)
        rowmax = fmaxf(rowmax, s_max[i]);

    // ---- Second register pass: sumexp, masked logit sum, positive count ----
    float se = 0.0f;   // sum of exp(x - rowmax)
    float sp = 0.0f;   // sum of logits at positive labels
    int   cnt = 0;     // number of positive labels

    #pragma unroll
    for (int i = 0; i < 16; i++) {
        se += __expf(v[i] - rowmax);
        if ((mask >> i) & 1u) { sp += v[i]; cnt++; }
    }

    // ---- Block-reduce se / sp / cnt ----
    __shared__ float s_se[THREADS / 32];
    __shared__ float s_sp[THREADS / 32];
    __shared__ int   s_cnt[THREADS / 32];

    #pragma unroll
    for (int o = 16; o > 0; o >>= 1) {
        se  += __shfl_xor_sync(0xffffffffu, se, o);
        sp  += __shfl_xor_sync(0xffffffffu, sp, o);
        cnt += __shfl_xor_sync(0xffffffffu, cnt, o);
    }
    if ((t & 31) == 0) {
        s_se[t >> 5]  = se;
        s_sp[t >> 5]  = sp;
        s_cnt[t >> 5] = cnt;
    }
    __syncthreads();

    if (t == 0) {
        float tse = 0.0f, tsp = 0.0f;
        int   tc  = 0;
        #pragma unroll
        for (int i = 0; i < THREADS / 32; i++) {
            tse += s_se[i];
            tsp += s_sp[i];
            tc  += s_cnt[i];
        }
        // per_row = count * lse - sum_positive_logits
        float lse = logf(tse) + rowmax;
        g_rowloss[row] = (float)tc * lse - tsp;
    }
}

// Deterministic final mean over rows (double accumulation, fixed order).
__global__ __launch_bounds__(512)
void mpnl_reduce_kernel(float* __restrict__ out)
{
    const int t = threadIdx.x;
    double s = 0.0;
    for (int i = t; i < NB; i += 512)
        s += (double)g_rowloss[i];

    __shared__ double sd[512 / 32];
    #pragma unroll
    for (int o = 16; o > 0; o >>= 1)
        s += __shfl_xor_sync(0xffffffffu, s, o);
    if ((t & 31) == 0) sd[t >> 5] = s;
    __syncthreads();

    if (t == 0) {
        double tot = 0.0;
        #pragma unroll
        for (int i = 0; i < 512 / 32; i++)
            tot += sd[i];
        out[0] = (float)(tot / (double)NB);
    }
}

extern "C" void kernel_launch(void* const* d_in, const int* in_sizes, int n_in,
                              void* d_out, int out_size)
{
    const float* logits = (const float*)d_in[0];
    const int*   labels = (const int*)d_in[1];
    float*       out    = (float*)d_out;

    mpnl_row_kernel<<<NB, THREADS>>>(logits, labels);
    mpnl_reduce_kernel<<<1, 512>>>(out);
}

// round 6
// speedup vs baseline: 1.0027x; 1.0027x over previous
#include <cuda_runtime.h>
#include <cuda_bf16.h>
#include <math_constants.h>

#define NB 16384      // batch rows
#define NP 4096       // passages per row
#define THREADS 256
#define CHUNKS 4      // 4 float4 per thread: 256 threads * 4 * 4 floats = 4096

// Per-row loss scratch (no dynamic allocation allowed).
__device__ float g_rowloss[NB];

__global__ __launch_bounds__(THREADS)
void mpnl_row_kernel(const float* __restrict__ logits,
                     const int* __restrict__ labels)   // int32: JAX demotes int64
{
    const int row = blockIdx.x;
    const int t   = threadIdx.x;

    const float4* lg4 = (const float4*)(logits + (size_t)row * NP);
    const int4*   lb4 = (const int4*)(labels + (size_t)row * NP);

    // Load 16 logits + 16 labels per thread; stash logits in registers,
    // labels as a 16-bit mask. Coalesced 16B accesses, same index stream
    // for both tensors.
    float v[16];
    unsigned mask = 0u;
    float m = -CUDART_INF_F;

    #pragma unroll
    for (int c = 0; c < CHUNKS; c++) {
        const int idx = c * THREADS + t;          // vec4 index within row
        float4 f = lg4[idx];
        int4   l = lb4[idx];

        v[c * 4 + 0] = f.x;
        v[c * 4 + 1] = f.y;
        v[c * 4 + 2] = f.z;
        v[c * 4 + 3] = f.w;
        if (l.x != 0) mask |= 1u << (c * 4 + 0);
        if (l.y != 0) mask |= 1u << (c * 4 + 1);
        if (l.z != 0) mask |= 1u << (c * 4 + 2);
        if (l.w != 0) mask |= 1u << (c * 4 + 3);

        m = fmaxf(m, fmaxf(fmaxf(f.x, f.y), fmaxf(f.z, f.w)));
    }

    // ---- Block-reduce the row max ----
    __shared__ float s_max[THREADS / 32];
    #pragma unroll
    for (int o = 16; o > 0; o >>= 1)
        m = fmaxf(m, __shfl_xor_sync(0xffffffffu, m, o));
    if ((t & 31) == 0) s_max[t >> 5] = m;
    __syncthreads();

    float rowmax = s_max[0];
    #pragma unroll
    for (int i = 1; i < THREADS / 32; i++)
        rowmax = fmaxf(rowmax, s_max[i]);

    // ---- Second register pass: sumexp, masked logit sum, positive count ----
    float se = 0.0f;   // sum of exp(x - rowmax)
    float sp = 0.0f;   // sum of logits at positive labels
    int   cnt = 0;     // number of positive labels

    #pragma unroll
    for (int i = 0; i < 16; i++) {
        se += __expf(v[i] - rowmax);
        if ((mask >> i) & 1u) { sp += v[i]; cnt++; }
    }

    // ---- Block-reduce se / sp / cnt ----
    __shared__ float s_se[THREADS / 32];
    __shared__ float s_sp[THREADS / 32];
    __shared__ int   s_cnt[THREADS / 32];

    #pragma unroll
    for (int o = 16; o > 0; o >>= 1) {
        se  += __shfl_xor_sync(0xffffffffu, se, o);
        sp  += __shfl_xor_sync(0xffffffffu, sp, o);
        cnt += __shfl_xor_sync(0xffffffffu, cnt, o);
    }
    if ((t & 31) == 0) {
        s_se[t >> 5]  = se;
        s_sp[t >> 5]  = sp;
        s_cnt[t >> 5] = cnt;
    }
    __syncthreads();

    if (t == 0) {
        float tse = 0.0f, tsp = 0.0f;
        int   tc  = 0;
        #pragma unroll
        for (int i = 0; i < THREADS / 32; i++) {
            tse += s_se[i];
            tsp += s_sp[i];
            tc  += s_cnt[i];
        }
        // per_row = count * lse - sum_positive_logits
        float lse = logf(tse) + rowmax;
        g_rowloss[row] = (float)tc * lse - tsp;
    }
}

// Deterministic final mean over rows (double accumulation, fixed order).
__global__ __launch_bounds__(512)
void mpnl_reduce_kernel(float* __restrict__ out)
{
    const int t = threadIdx.x;
    double s = 0.0;
    for (int i = t; i < NB; i += 512)
        s += (double)g_rowloss[i];

    __shared__ double sd[512 / 32];
    #pragma unroll
    for (int o = 16; o > 0; o >>= 1)
        s += __shfl_xor_sync(0xffffffffu, s, o);
    if ((t & 31) == 0) sd[t >> 5] = s;
    __syncthreads();

    if (t == 0) {
        double tot = 0.0;
        #pragma unroll
        for (int i = 0; i < 512 / 32; i++)
            tot += sd[i];
        out[0] = (float)(tot / (double)NB);
    }
}

extern "C" void kernel_launch(void* const* d_in, const int* in_sizes, int n_in,
                              void* d_out, int out_size)
{
    const float* logits = (const float*)d_in[0];
    const int*   labels = (const int*)d_in[1];
    float*       out    = (float*)d_out;

    mpnl_row_kernel<<<NB, THREADS>>>(logits, labels);
    mpnl_reduce_kernel<<<1, 512>>>(out);
}